// round 7
// baseline (speedup 1.0000x reference)
#include <cuda_runtime.h>
#include <cuda_fp16.h>
#include <cstdint>
#include <cstring>

#define B_DIM   64
#define OUT_DIM 4096
#define IN_DIM  25088
#define NCLASS  32
#define SPLITS  9
#define KC      64                 // K elems per chunk (64 fp16 = 128B row)
#define TILE_M  128
#define NTILES  (OUT_DIM / TILE_M) // 32

// ---- static device scratch ----
__device__ float gPart[SPLITS * OUT_DIM * B_DIM];

// ======================= helpers =======================
__device__ __forceinline__ uint32_t smem_u32(const void* p) {
    uint32_t a;
    asm("{ .reg .u64 t; cvta.to.shared.u64 t, %1; cvt.u32.u64 %0, t; }" : "=r"(a) : "l"(p));
    return a;
}
__device__ __forceinline__ void ldsm_x4(uint32_t* r, uint32_t addr) {
    asm volatile("ldmatrix.sync.aligned.m8n8.x4.shared.b16 {%0,%1,%2,%3}, [%4];"
                 : "=r"(r[0]), "=r"(r[1]), "=r"(r[2]), "=r"(r[3]) : "r"(addr));
}
__device__ __forceinline__ void mma_f16(float* d, const uint32_t* a, const uint32_t* b) {
    asm volatile("mma.sync.aligned.m16n8k16.row.col.f32.f16.f16.f32 "
                 "{%0,%1,%2,%3}, {%4,%5,%6,%7}, {%8,%9}, {%0,%1,%2,%3};"
                 : "+f"(d[0]), "+f"(d[1]), "+f"(d[2]), "+f"(d[3])
                 : "r"(a[0]), "r"(a[1]), "r"(a[2]), "r"(a[3]), "r"(b[0]), "r"(b[1]));
}
__device__ __forceinline__ uint32_t swz(uint32_t bo) { return bo ^ ((bo >> 3) & 0x70); }
__device__ __forceinline__ uint32_t pack_h2(float a, float b) {
    __half2 p = make_half2(__float2half_rn(a), __float2half_rn(b));
    uint32_t u;
    memcpy(&u, &p, 4);
    return u;
}

// ======================= SMEM layout (per stage) =======================
#define W_OFF      0            // 128 x 64 fp16 = 16384
#define XH_OFF     16384        //  64 x 64 fp16 =  8192
#define STAGE_SZ   24576
#define SMEM_TOTAL (2 * STAGE_SZ)   // 49152

// ======================= Kernel 1: fused dequant + convert + GEMM =======================
struct LabelRegs { int4 lv[8]; };

__device__ __forceinline__ void fetch_labels(const int* __restrict__ labels, int tile,
                                             int chunk, int wid, int lane, LabelRegs& L) {
    const int k0 = chunk * KC;
    const int rsub = (lane >> 4);        // 0..1
    const int lx   = lane & 15;          // 16B index
    #pragma unroll
    for (int j = 0; j < 8; j++) {
        int r = j * 16 + wid * 2 + rsub;
        const int4* p = reinterpret_cast<const int4*>(
            labels + (size_t)(tile * TILE_M + r) * IN_DIM + k0) + lx;
        L.lv[j] = __ldcs(p);
    }
}

__device__ __forceinline__ void store_chunk(uint32_t tab, const LabelRegs& L,
                                            const float* __restrict__ x,
                                            char* stage, int chunk, int wid, int lane) {
    const int rsub = (lane >> 4);
    const int lx   = lane & 15;
    // W tile: dequant via lane-table shfl, STS.64 (4 fp16)
    #pragma unroll
    for (int j = 0; j < 8; j++) {
        int r = j * 16 + wid * 2 + rsub;
        int4 lv = L.lv[j];
        uint32_t v0 = __shfl_sync(0xffffffffu, tab, lv.x & 31);
        uint32_t v1 = __shfl_sync(0xffffffffu, tab, lv.y & 31);
        uint32_t v2 = __shfl_sync(0xffffffffu, tab, lv.z & 31);
        uint32_t v3 = __shfl_sync(0xffffffffu, tab, lv.w & 31);
        uint32_t h01 = __byte_perm(v0, v1, 0x5410);
        uint32_t h23 = __byte_perm(v2, v3, 0x5410);
        uint32_t sw = swz((uint32_t)(r * 128 + lx * 8));
        *reinterpret_cast<uint2*>(stage + W_OFF + sw) = make_uint2(h01, h23);
    }
    // x tile: load f32 from global (L2-resident), convert to fp16, STS.128
    const int k0 = chunk * KC;
    const int xr = lane >> 3;               // 0..3 subrow
    const int xc = (lane & 7) * 8;          // f32 column offset (8 floats per lane)
    #pragma unroll
    for (int j = 0; j < 2; j++) {
        int row = wid * 8 + j * 4 + xr;
        const float4* p = reinterpret_cast<const float4*>(
            x + (size_t)row * IN_DIM + k0 + xc);
        float4 v0 = __ldg(p);
        float4 v1 = __ldg(p + 1);
        uint4 u = make_uint4(pack_h2(v0.x, v0.y), pack_h2(v0.z, v0.w),
                             pack_h2(v1.x, v1.y), pack_h2(v1.z, v1.w));
        uint32_t sw = swz((uint32_t)(row * 128 + (lane & 7) * 16));
        *reinterpret_cast<uint4*>(stage + XH_OFF + sw) = u;
    }
}

__global__ void __launch_bounds__(256, 2) gemm_kernel(const int* __restrict__ labels,
                                                      const float* __restrict__ x,
                                                      const float* __restrict__ cent) {
    extern __shared__ char smem[];
    const uint32_t sb = smem_u32(smem);
    const int tid  = threadIdx.x;
    const int wid  = tid >> 5;
    const int lane = tid & 31;
    const int tile  = blockIdx.x;
    const int slice = blockIdx.y;

    const int m0 = (wid & 3) * 32;   // warp M offset within 128
    const int n0 = (wid >> 2) * 32;  // warp N offset within 64

    // per-lane codebook entry (fp16 of centroid[lane]) — built locally, no prep kernel
    uint32_t tab;
    {
        __half h = __float2half_rn(__ldg(&cent[lane]));
        unsigned short hb;
        memcpy(&hb, &h, 2);
        tab = (uint32_t)hb;
    }

    // chunk range: first 5 slices 44 chunks, rest 43 (total 392)
    const int c0  = slice * 43 + (slice < 5 ? slice : 5);
    const int nch = 43 + (slice < 5 ? 1 : 0);

    float acc[2][4][4];
    #pragma unroll
    for (int mi = 0; mi < 2; mi++)
        #pragma unroll
        for (int ni = 0; ni < 4; ni++)
            #pragma unroll
            for (int e = 0; e < 4; e++) acc[mi][ni][e] = 0.0f;

    // per-lane ldmatrix address components
    const int rowA = lane & 15;
    const int kA   = (lane >> 4) * 16;
    const int rowB = (lane & 7) + ((lane >> 4) & 1) * 8;
    const int kB   = ((lane >> 3) & 1) * 16;

    LabelRegs L;
    fetch_labels(labels, tile, c0, wid, lane, L);
    store_chunk(tab, L, x, smem, c0, wid, lane);
    __syncthreads();

    for (int i = 0; i < nch; i++) {
        // prefetch next chunk's labels into regs BEFORE compute (hide DRAM latency)
        if (i + 1 < nch) fetch_labels(labels, tile, c0 + i + 1, wid, lane, L);

        const uint32_t s_w  = sb + (uint32_t)(i & 1) * STAGE_SZ + W_OFF;
        const uint32_t s_xh = s_w + XH_OFF;

        #pragma unroll
        for (int k = 0; k < 4; k++) {
            const int kb = k * 32;  // 16 fp16 = 32 bytes
            uint32_t a[2][4], bh[8];
            #pragma unroll
            for (int mi = 0; mi < 2; mi++)
                ldsm_x4(a[mi], s_w + swz((uint32_t)((m0 + mi * 16 + rowA) * 128 + kb + kA)));
            {
                uint32_t bo0 = (uint32_t)((n0 + rowB) * 128 + kb + kB);
                uint32_t bo1 = (uint32_t)((n0 + 16 + rowB) * 128 + kb + kB);
                ldsm_x4(bh,     s_xh + swz(bo0));
                ldsm_x4(bh + 4, s_xh + swz(bo1));
            }
            #pragma unroll
            for (int mi = 0; mi < 2; mi++)
                #pragma unroll
                for (int ni = 0; ni < 4; ni++)
                    mma_f16(acc[mi][ni], a[mi], &bh[ni * 2]);
        }

        if (i + 1 < nch)
            store_chunk(tab, L, x, smem + ((i + 1) & 1) * STAGE_SZ, c0 + i + 1, wid, lane);
        __syncthreads();
    }

    // epilogue: acc -> gPart[slice][o][b]
    #pragma unroll
    for (int mi = 0; mi < 2; mi++)
        #pragma unroll
        for (int ni = 0; ni < 4; ni++) {
            int row = tile * TILE_M + m0 + mi * 16 + (lane >> 2);
            int col = n0 + ni * 8 + (lane & 3) * 2;
            float* base = &gPart[((size_t)slice * OUT_DIM + row) * B_DIM + col];
            reinterpret_cast<float2*>(base)[0]             = make_float2(acc[mi][ni][0], acc[mi][ni][1]);
            reinterpret_cast<float2*>(base + 8 * B_DIM)[0] = make_float2(acc[mi][ni][2], acc[mi][ni][3]);
        }
}

// ======================= Kernel 2: reduce + bias, transposed via smem =======================
__global__ void reduce_kernel(const float* __restrict__ bias, float* __restrict__ out) {
    __shared__ float tile[64][65];
    const int o0 = blockIdx.x * 64;
    const int t  = threadIdx.x;
    {
        const int b = t & 63, osub = t >> 6;
        #pragma unroll
        for (int oo = osub; oo < 64; oo += 4) {
            const int o = o0 + oo;
            float s = __ldg(&bias[o]);
            #pragma unroll
            for (int sl = 0; sl < SPLITS; sl++)
                s += __ldcs(&gPart[((size_t)sl * OUT_DIM + o) * B_DIM + b]);
            tile[oo][b] = s;
        }
    }
    __syncthreads();
    {
        const int op = t & 63, bsub = t >> 6;
        #pragma unroll
        for (int bb = bsub; bb < 64; bb += 4)
            out[(size_t)bb * OUT_DIM + o0 + op] = tile[op][bb];
    }
}

// ======================= launch =======================
extern "C" void kernel_launch(void* const* d_in, const int* in_sizes, int n_in,
                              void* d_out, int out_size) {
    const float* x      = (const float*)d_in[0];
    const int*   labels = (const int*)d_in[1];
    const float* cent   = (const float*)d_in[2];
    const float* bias   = (const float*)d_in[3];
    float*       out    = (float*)d_out;

    cudaFuncSetAttribute(gemm_kernel, cudaFuncAttributeMaxDynamicSharedMemorySize, SMEM_TOTAL);

    gemm_kernel<<<dim3(NTILES, SPLITS), 256, SMEM_TOTAL>>>(labels, x, cent);
    reduce_kernel<<<OUT_DIM / 64, 256>>>(bias, out);
}

// round 8
// speedup vs baseline: 1.1295x; 1.1295x over previous
#include <cuda_runtime.h>
#include <cuda_fp16.h>
#include <cstdint>
#include <cstring>

#define B_DIM   64
#define OUT_DIM 4096
#define IN_DIM  25088
#define NCLASS  32
#define SPLITS  9
#define KC      64                 // K elems per chunk (64 fp16 = 128B row)
#define TILE_M  128
#define NTILES  (OUT_DIM / TILE_M) // 32

// ---- static device scratch ----
__device__ uint32_t gXh[B_DIM * (IN_DIM / 2)];    // x fp16x2 packed
__device__ uint32_t gTab[NCLASS];                 // fp16(centroid) in low 16 bits
__device__ float    gPart[SPLITS * OUT_DIM * B_DIM];

// ======================= helpers =======================
__device__ __forceinline__ uint32_t smem_u32(const void* p) {
    uint32_t a;
    asm("{ .reg .u64 t; cvta.to.shared.u64 t, %1; cvt.u32.u64 %0, t; }" : "=r"(a) : "l"(p));
    return a;
}
__device__ __forceinline__ void ldsm_x4(uint32_t* r, uint32_t addr) {
    asm volatile("ldmatrix.sync.aligned.m8n8.x4.shared.b16 {%0,%1,%2,%3}, [%4];"
                 : "=r"(r[0]), "=r"(r[1]), "=r"(r[2]), "=r"(r[3]) : "r"(addr));
}
__device__ __forceinline__ void mma_f16(float* d, const uint32_t* a, const uint32_t* b) {
    asm volatile("mma.sync.aligned.m16n8k16.row.col.f32.f16.f16.f32 "
                 "{%0,%1,%2,%3}, {%4,%5,%6,%7}, {%8,%9}, {%0,%1,%2,%3};"
                 : "+f"(d[0]), "+f"(d[1]), "+f"(d[2]), "+f"(d[3])
                 : "r"(a[0]), "r"(a[1]), "r"(a[2]), "r"(a[3]), "r"(b[0]), "r"(b[1]));
}
__device__ __forceinline__ uint32_t swz(uint32_t bo) { return bo ^ ((bo >> 3) & 0x70); }

// ======================= SMEM layout (per stage) =======================
#define W_OFF      0            // 128 x 64 fp16 = 16384
#define XH_OFF     16384        //  64 x 64 fp16 =  8192
#define STAGE_SZ   24576
#define SMEM_TOTAL (2 * STAGE_SZ)   // 49152

// ======================= Kernel 0: x -> fp16, codebook table =======================
__global__ void prep_kernel(const float* __restrict__ x, const float* __restrict__ cent) {
    if (blockIdx.x == 0 && threadIdx.x < NCLASS) {
        __half h = __float2half_rn(cent[threadIdx.x]);
        unsigned short hb;
        memcpy(&hb, &h, 2);
        gTab[threadIdx.x] = (uint32_t)hb;
    }
    const int base = blockIdx.x * 512 + threadIdx.x;   // 2 float4 per thread (MLP=2)
    float4 v[2];
    #pragma unroll
    for (int j = 0; j < 2; j++)
        v[j] = reinterpret_cast<const float4*>(x)[base + j * 256];
    #pragma unroll
    for (int j = 0; j < 2; j++) {
        __half2 p0 = make_half2(__float2half_rn(v[j].x), __float2half_rn(v[j].y));
        __half2 p1 = make_half2(__float2half_rn(v[j].z), __float2half_rn(v[j].w));
        uint32_t u0, u1;
        memcpy(&u0, &p0, 4); memcpy(&u1, &p1, 4);
        reinterpret_cast<uint2*>(gXh)[base + j * 256] = make_uint2(u0, u1);
    }
}

// ======================= Kernel 1: fused dequant + GEMM (R4-proven) =======================
struct LabelRegs { int4 lv[8]; };

__device__ __forceinline__ void fetch_labels(const int* __restrict__ labels, int tile,
                                             int chunk, int wid, int lane, LabelRegs& L) {
    const int k0 = chunk * KC;
    const int rsub = (lane >> 4);        // 0..1
    const int lx   = lane & 15;          // 16B index
    #pragma unroll
    for (int j = 0; j < 8; j++) {
        int r = j * 16 + wid * 2 + rsub;
        const int4* p = reinterpret_cast<const int4*>(
            labels + (size_t)(tile * TILE_M + r) * IN_DIM + k0) + lx;
        L.lv[j] = __ldcs(p);
    }
}

__device__ __forceinline__ void store_chunk(uint32_t tab, const LabelRegs& L,
                                            char* stage, int chunk, int wid, int lane) {
    const int rsub = (lane >> 4);
    const int lx   = lane & 15;
    // W tile: dequant via lane-table shfl, STS.64 (4 fp16)
    #pragma unroll
    for (int j = 0; j < 8; j++) {
        int r = j * 16 + wid * 2 + rsub;
        int4 lv = L.lv[j];
        uint32_t v0 = __shfl_sync(0xffffffffu, tab, lv.x & 31);
        uint32_t v1 = __shfl_sync(0xffffffffu, tab, lv.y & 31);
        uint32_t v2 = __shfl_sync(0xffffffffu, tab, lv.z & 31);
        uint32_t v3 = __shfl_sync(0xffffffffu, tab, lv.w & 31);
        uint32_t h01 = __byte_perm(v0, v1, 0x5410);
        uint32_t h23 = __byte_perm(v2, v3, 0x5410);
        uint32_t sw = swz((uint32_t)(r * 128 + lx * 8));
        *reinterpret_cast<uint2*>(stage + W_OFF + sw) = make_uint2(h01, h23);
    }
    // x tile: 64 rows x 128B, LDG.128/STS.128 (pre-packed fp16)
    const int k0h = (chunk * KC) >> 1;       // uint32 index within row
    const int xr  = lane >> 3;               // 0..3 subrow
    const int xc  = (lane & 7) * 4;          // uint32 offset (16B granule)
    #pragma unroll
    for (int j = 0; j < 2; j++) {
        int row = wid * 8 + j * 4 + xr;
        size_t gi = (size_t)row * (IN_DIM / 2) + k0h + xc;
        uint32_t sw = swz((uint32_t)(row * 128 + xc * 4));
        *reinterpret_cast<uint4*>(stage + XH_OFF + sw) =
            *reinterpret_cast<const uint4*>(&gXh[gi]);
    }
}

__global__ void __launch_bounds__(256, 2) gemm_kernel(const int* __restrict__ labels) {
    extern __shared__ char smem[];
    const uint32_t sb = smem_u32(smem);
    const int tid  = threadIdx.x;
    const int wid  = tid >> 5;
    const int lane = tid & 31;
    const int tile  = blockIdx.x;
    const int slice = blockIdx.y;

    const int m0 = (wid & 3) * 32;   // warp M offset within 128
    const int n0 = (wid >> 2) * 32;  // warp N offset within 64

    const uint32_t tab = gTab[lane];

    // chunk range: first 5 slices 44 chunks, rest 43 (total 392)
    const int c0  = slice * 43 + (slice < 5 ? slice : 5);
    const int nch = 43 + (slice < 5 ? 1 : 0);

    float acc[2][4][4];
    #pragma unroll
    for (int mi = 0; mi < 2; mi++)
        #pragma unroll
        for (int ni = 0; ni < 4; ni++)
            #pragma unroll
            for (int e = 0; e < 4; e++) acc[mi][ni][e] = 0.0f;

    // per-lane ldmatrix address components
    const int rowA = lane & 15;
    const int kA   = (lane >> 4) * 16;
    const int rowB = (lane & 7) + ((lane >> 4) & 1) * 8;
    const int kB   = ((lane >> 3) & 1) * 16;

    LabelRegs L;
    fetch_labels(labels, tile, c0, wid, lane, L);
    store_chunk(tab, L, smem, c0, wid, lane);
    __syncthreads();

    for (int i = 0; i < nch; i++) {
        // prefetch next chunk's labels into regs BEFORE compute (hide DRAM latency)
        if (i + 1 < nch) fetch_labels(labels, tile, c0 + i + 1, wid, lane, L);

        const uint32_t s_w  = sb + (uint32_t)(i & 1) * STAGE_SZ + W_OFF;
        const uint32_t s_xh = s_w + XH_OFF;

        #pragma unroll
        for (int k = 0; k < 4; k++) {
            const int kb = k * 32;  // 16 fp16 = 32 bytes
            uint32_t a[2][4], bh[8];
            #pragma unroll
            for (int mi = 0; mi < 2; mi++)
                ldsm_x4(a[mi], s_w + swz((uint32_t)((m0 + mi * 16 + rowA) * 128 + kb + kA)));
            {
                uint32_t bo0 = (uint32_t)((n0 + rowB) * 128 + kb + kB);
                uint32_t bo1 = (uint32_t)((n0 + 16 + rowB) * 128 + kb + kB);
                ldsm_x4(bh,     s_xh + swz(bo0));
                ldsm_x4(bh + 4, s_xh + swz(bo1));
            }
            #pragma unroll
            for (int mi = 0; mi < 2; mi++)
                #pragma unroll
                for (int ni = 0; ni < 4; ni++)
                    mma_f16(acc[mi][ni], a[mi], &bh[ni * 2]);
        }

        if (i + 1 < nch)
            store_chunk(tab, L, smem + ((i + 1) & 1) * STAGE_SZ, c0 + i + 1, wid, lane);
        __syncthreads();
    }

    // epilogue: acc -> gPart[slice][o][b]
    #pragma unroll
    for (int mi = 0; mi < 2; mi++)
        #pragma unroll
        for (int ni = 0; ni < 4; ni++) {
            int row = tile * TILE_M + m0 + mi * 16 + (lane >> 2);
            int col = n0 + ni * 8 + (lane & 3) * 2;
            float* base = &gPart[((size_t)slice * OUT_DIM + row) * B_DIM + col];
            reinterpret_cast<float2*>(base)[0]             = make_float2(acc[mi][ni][0], acc[mi][ni][1]);
            reinterpret_cast<float2*>(base + 8 * B_DIM)[0] = make_float2(acc[mi][ni][2], acc[mi][ni][3]);
        }
}

// ======================= Kernel 2: reduce + bias (256 blocks, 16-o tiles) =======================
__global__ void reduce_kernel(const float* __restrict__ bias, float* __restrict__ out) {
    __shared__ float tile[16][65];
    const int o0 = blockIdx.x * 16;
    const int t  = threadIdx.x;
    {
        const int b = t & 63;             // 64 b lanes
        const int osub = t >> 6;          // 4 o sub-slots
        #pragma unroll
        for (int oo = osub; oo < 16; oo += 4) {
            const int o = o0 + oo;
            float s = __ldg(&bias[o]);
            #pragma unroll
            for (int sl = 0; sl < SPLITS; sl++)
                s += __ldcs(&gPart[((size_t)sl * OUT_DIM + o) * B_DIM + b]);
            tile[oo][b] = s;
        }
    }
    __syncthreads();
    {
        const int op = t & 15;            // 16 o positions (consecutive in out)
        const int bsub = t >> 4;          // 16 b per pass
        #pragma unroll
        for (int bb = bsub; bb < 64; bb += 16)
            out[(size_t)bb * OUT_DIM + o0 + op] = tile[op][bb];
    }
}

// ======================= launch =======================
extern "C" void kernel_launch(void* const* d_in, const int* in_sizes, int n_in,
                              void* d_out, int out_size) {
    const float* x      = (const float*)d_in[0];
    const int*   labels = (const int*)d_in[1];
    const float* cent   = (const float*)d_in[2];
    const float* bias   = (const float*)d_in[3];
    float*       out    = (float*)d_out;

    cudaFuncSetAttribute(gemm_kernel, cudaFuncAttributeMaxDynamicSharedMemorySize, SMEM_TOTAL);

    prep_kernel<<<B_DIM * (IN_DIM / 4) / 512, 256>>>(x, cent);
    gemm_kernel<<<dim3(NTILES, SPLITS), 256, SMEM_TOTAL>>>(labels);
    reduce_kernel<<<OUT_DIM / 16, 256>>>(bias, out);
}